// round 6
// baseline (speedup 1.0000x reference)
#include <cuda_runtime.h>

// DySample fused: B=16, C=64, H=W=128, scale=2, groups=4
// Phase 1 (block = one (b,h) row): off = (x . w_off^T + b_off)*0.25 + init -> smem
// Phase 2: thread = pixel pair (2k,2k+1) x one group g x 16 channels.
//   init sign s = (g&1)? ri : rj => tap window = s-diagonal 2x2 of the 3x3;
//   the two pixels' windows union to a 3x4 patch loaded as 9 LDG.64.
//   Both pixels computed together with packed f32x2 FMA; stores are STG.128.
//   Cold exact-repair handles positions escaping the predicted window.

#define HW 16384

__device__ __forceinline__ unsigned long long pack2(float a, float b) {
    unsigned long long r;
    asm("mov.b64 %0, {%1, %2};" : "=l"(r) : "f"(a), "f"(b));
    return r;
}
__device__ __forceinline__ void ffma2(unsigned long long& d,
                                      unsigned long long a, unsigned long long b) {
    asm("fma.rn.f32x2 %0, %1, %2, %0;" : "+l"(d) : "l"(a), "l"(b));
}
__device__ __forceinline__ unsigned long long mul2(unsigned long long a,
                                                   unsigned long long b) {
    unsigned long long d;
    asm("mul.rn.f32x2 %0, %1, %2;" : "=l"(d) : "l"(a), "l"(b));
    return d;
}
__device__ __forceinline__ float2 unpack2(unsigned long long v) {
    float2 f;
    asm("mov.b64 {%0, %1}, %2;" : "=f"(f.x), "=f"(f.y) : "l"(v));
    return f;
}
__device__ __forceinline__ float clampf(float v, float lo, float hi) {
    return fminf(fmaxf(v, lo), hi);
}

// ---------------------------------------------------------------------------
// Phase 2 worker, GG = g & 1 compile-time (warps are uniform in g).
// ---------------------------------------------------------------------------
template <int GG>
__device__ __forceinline__ void sample_group(
    const float* __restrict__ offs,   // smem [32][128]
    const float* __restrict__ x,
    float* __restrict__ out,
    int b, int h, int g, int k)
{
    const int w0 = k << 1;
    const float fh = (float)h;
    const int rm = (max(h - 1, 0)) << 7, rc = h << 7, rp = (min(h + 1, 127)) << 7;
    const int colL = max(w0 - 2, 0);
    const int colM = w0;
    const int colR = min(w0 + 2, 126);
    const bool k0 = (k == 0), k63 = (k == 63);
    const int hm = max(h - 1, 0), hp = min(h + 1, 127);

    // ---- position setup: packed weights per pos, validity bits -------------
    unsigned long long PA00[4], PA01[4], PA10[4], PA11[4];
    int bad = 0;
    #pragma unroll
    for (int pos = 0; pos < 4; pos++) {
        const int ri = pos >> 1, rj = pos & 1;
        const int s = GG ? ri : rj;           // compile-time
        const int o = (g << 2) + pos;
        const float2 ox2 = *reinterpret_cast<const float2*>(&offs[(o << 7) + w0]);
        const float2 oy2 = *reinterpret_cast<const float2*>(&offs[((o + 16) << 7) + w0]);
        float a00[2], a01[2], a10[2], a11[2];
        #pragma unroll
        for (int p = 0; p < 2; p++) {
            const int wp_ = w0 + p;
            const float fwp = (float)wp_;
            const float offx = p ? ox2.y : ox2.x;
            const float offy = p ? oy2.y : oy2.x;
            const float ix = clampf(fwp + offx, 0.0f, 127.0f);
            const float iy = clampf(fh + offy, 0.0f, 127.0f);
            const float x0f = floorf(ix), y0f = floorf(iy);
            const float wx = ix - x0f, wy = iy - y0f;
            const int x0 = (int)x0f, y0 = (int)y0f;
            const int x1 = min(x0 + 1, 127), y1 = min(y0 + 1, 127);
            const int cx0 = s ? wp_ : max(wp_ - 1, 0);
            const int cx1 = s ? min(wp_ + 1, 127) : wp_;
            const int cy0 = s ? h : hm;
            const int cy1 = s ? hp : h;
            const bool ok = (x0 == cx0) && (wx == 0.0f || x1 == cx1)
                         && (y0 == cy0) && (wy == 0.0f || y1 == cy1);
            if (!ok) bad |= 1 << (pos * 2 + p);
            a00[p] = (1.0f - wy) * (1.0f - wx);
            a01[p] = (1.0f - wy) * wx;
            a10[p] = wy * (1.0f - wx);
            a11[p] = wy * wx;
        }
        PA00[pos] = pack2(a00[0], a00[1]);
        PA01[pos] = pack2(a01[0], a01[1]);
        PA10[pos] = pack2(a10[0], a10[1]);
        PA11[pos] = pack2(a11[0], a11[1]);
    }

    const int cbase = b * 64 + (g << 4);
    const float* pb = x + (cbase << 14);
    float* db = out + (cbase << 16) + (h << 9) + (k << 2);

    // ---- fast path: 16 channels, 9 LDG.64 taps -> 8 outputs (2 STG.128) ----
    {
        const float* p = pb;
        float* dst = db;
        #pragma unroll 2
        for (int cc = 0; cc < 16; cc++) {
            const float2 L0 = __ldg(reinterpret_cast<const float2*>(p + rm + colL));
            const float2 M0 = __ldg(reinterpret_cast<const float2*>(p + rm + colM));
            const float2 R0 = __ldg(reinterpret_cast<const float2*>(p + rm + colR));
            const float2 L1 = __ldg(reinterpret_cast<const float2*>(p + rc + colL));
            const float2 M1 = __ldg(reinterpret_cast<const float2*>(p + rc + colM));
            const float2 R1 = __ldg(reinterpret_cast<const float2*>(p + rc + colR));
            const float2 L2 = __ldg(reinterpret_cast<const float2*>(p + rp + colL));
            const float2 M2 = __ldg(reinterpret_cast<const float2*>(p + rp + colM));
            const float2 R2 = __ldg(reinterpret_cast<const float2*>(p + rp + colR));

            // per-row cols: v0 = max(w0-1,0), v1 = w0, v2 = w0+1, v3 = min(w0+2,127)
            const float v00 = k0 ? L0.x : L0.y, v03 = k63 ? R0.y : R0.x;
            const float v10 = k0 ? L1.x : L1.y, v13 = k63 ? R1.y : R1.x;
            const float v20 = k0 ? L2.x : L2.y, v23 = k63 ? R2.y : R2.x;

            const unsigned long long P0a = pack2(v00, M0.x);
            const unsigned long long P0b = pack2(M0.x, M0.y);
            const unsigned long long P1a = pack2(v10, M1.x);
            const unsigned long long P1b = pack2(M1.x, M1.y);
            const unsigned long long P1c = pack2(M1.y, v13);
            const unsigned long long P2b = pack2(M2.x, M2.y);
            const unsigned long long P2c = pack2(M2.y, v23);
            (void)v20; (void)v03;  // v20/v03 unused (windows never need them)

            unsigned long long V[4];
            #pragma unroll
            for (int pos = 0; pos < 4; pos++) {
                const int s = GG ? (pos >> 1) : (pos & 1);  // compile-time
                const unsigned long long T00 = s ? P1b : P0a;
                const unsigned long long T01 = s ? P1c : P0b;
                const unsigned long long T10 = s ? P2b : P1a;
                const unsigned long long T11 = s ? P2c : P1b;
                unsigned long long acc = mul2(PA00[pos], T00);
                ffma2(acc, PA01[pos], T01);
                ffma2(acc, PA10[pos], T10);
                ffma2(acc, PA11[pos], T11);
                V[pos] = acc;
            }
            const float2 V0 = unpack2(V[0]), V1 = unpack2(V[1]);
            const float2 V2 = unpack2(V[2]), V3 = unpack2(V[3]);
            *reinterpret_cast<float4*>(dst) =
                make_float4(V0.x, V1.x, V0.y, V1.y);          // row Y=2h
            *reinterpret_cast<float4*>(dst + 256) =
                make_float4(V2.x, V3.x, V2.y, V3.y);          // row Y=2h+1
            p   += HW;
            dst += 65536;
        }
    }

    // ---- cold exact repair --------------------------------------------------
    if (bad) {
        for (int pos = 0; pos < 4; pos++) {
            const int ri = pos >> 1, rj = pos & 1;
            const int o = (g << 2) + pos;
            for (int p_ = 0; p_ < 2; p_++) {
                if (!(bad & (1 << (pos * 2 + p_)))) continue;
                const int wp_ = w0 + p_;
                const float offx = offs[(o << 7) + wp_];
                const float offy = offs[((o + 16) << 7) + wp_];
                const float ix = clampf((float)wp_ + offx, 0.0f, 127.0f);
                const float iy = clampf(fh + offy, 0.0f, 127.0f);
                const float x0f = floorf(ix), y0f = floorf(iy);
                const float wx = ix - x0f, wy = iy - y0f;
                const int x0 = (int)x0f, y0 = (int)y0f;
                const int x1 = min(x0 + 1, 127), y1 = min(y0 + 1, 127);
                const float* p = pb;
                float* dst = db + ri * 256 + (p_ << 1) + rj;
                for (int cc = 0; cc < 16; cc++) {
                    const float u00 = __ldg(p + (y0 << 7) + x0);
                    const float u01 = __ldg(p + (y0 << 7) + x1);
                    const float u10 = __ldg(p + (y1 << 7) + x0);
                    const float u11 = __ldg(p + (y1 << 7) + x1);
                    *dst = (1.0f - wy) * ((1.0f - wx) * u00 + wx * u01)
                         + wy * ((1.0f - wx) * u10 + wx * u11);
                    p += HW;
                    dst += 65536;
                }
            }
        }
    }
}

__global__ __launch_bounds__(256) void dysample_fused(
    const float* __restrict__ x,
    const float* __restrict__ w_off,
    const float* __restrict__ b_off,
    float* __restrict__ out)
{
    __shared__ __align__(16) float ws[64 * 32];     // [c][o]
    __shared__ __align__(16) float offs[32 * 128];  // [o][w]

    const int h   = blockIdx.x;
    const int b   = blockIdx.y;
    const int tid = threadIdx.x;

    for (int i = tid; i < 2048; i += 256) {
        int c = i >> 5, o = i & 31;
        ws[i] = __ldg(&w_off[o * 64 + c]);
    }
    __syncthreads();

    // ---------------- Phase 1: 64->32 matvec for this row (packed f32x2) ----
    {
        const int p0 = (tid & 31) << 2;
        const int ob = (tid >> 5) << 2;
        const float* xb = x + ((b * 64) << 14) + (h << 7) + p0;

        unsigned long long acc[4][2];
        #pragma unroll
        for (int p = 0; p < 4; p++) { acc[p][0] = 0ull; acc[p][1] = 0ull; }

        #pragma unroll 4
        for (int c = 0; c < 64; c++) {
            const float4 xv = __ldg(reinterpret_cast<const float4*>(xb + (c << 14)));
            const unsigned long long w01 =
                *reinterpret_cast<const unsigned long long*>(&ws[c * 32 + ob]);
            const unsigned long long w23 =
                *reinterpret_cast<const unsigned long long*>(&ws[c * 32 + ob + 2]);
            unsigned long long xp;
            xp = pack2(xv.x, xv.x); ffma2(acc[0][0], xp, w01); ffma2(acc[0][1], xp, w23);
            xp = pack2(xv.y, xv.y); ffma2(acc[1][0], xp, w01); ffma2(acc[1][1], xp, w23);
            xp = pack2(xv.z, xv.z); ffma2(acc[2][0], xp, w01); ffma2(acc[2][1], xp, w23);
            xp = pack2(xv.w, xv.w); ffma2(acc[3][0], xp, w01); ffma2(acc[3][1], xp, w23);
        }

        #pragma unroll
        for (int oo = 0; oo < 4; oo++) {
            const int o = ob + oo;
            const float bias = __ldg(&b_off[o]);
            const int dd = (o >> 2) & 1, ii = (o >> 1) & 1, jj = o & 1;
            const float initv = 0.25f * (float)((((dd ? ii : jj) << 1)) - 1);
            float* dst = &offs[(o << 7) + p0];
            #pragma unroll
            for (int p = 0; p < 4; p++) {
                float2 v = unpack2(acc[p][oo >> 1]);
                float a = (oo & 1) ? v.y : v.x;
                dst[p] = (a + bias) * 0.25f + initv;
            }
        }
    }
    __syncthreads();

    // ---------------- Phase 2: bilinear sampling (pixel-pair) --------------
    const int k = tid & 63;
    const int g = tid >> 6;           // warp-uniform
    if ((g & 1) == 0)
        sample_group<0>(offs, x, out, b, h, g, k);
    else
        sample_group<1>(offs, x, out, b, h, g, k);
}

extern "C" void kernel_launch(void* const* d_in, const int* in_sizes, int n_in,
                              void* d_out, int out_size)
{
    const float* x     = (const float*)d_in[0];  // [16,64,128,128]
    const float* w_off = (const float*)d_in[1];  // [32,64]
    const float* b_off = (const float*)d_in[2];  // [32]
    float* out = (float*)d_out;                  // [16,64,256,256]

    dysample_fused<<<dim3(128, 16), 256>>>(x, w_off, b_off, out);
    (void)in_sizes; (void)n_in; (void)out_size;
}

// round 7
// speedup vs baseline: 1.1358x; 1.1358x over previous
#include <cuda_runtime.h>

// DySample fused (one kernel): B=16, C=64, H=W=128, scale=2, groups=4
// Phase 1 (block = one (b,h) row): off = (x . w_off^T + b_off)*0.25 + init -> smem
// Phase 2: out[b, g*16+cc, 2h+ri, 2w+rj] = bilinear(x[b,g*16+cc], iy, ix)
//   init sign s = (g&1)? ri : rj  =>  tap window = s-diagonal 2x2 of the
//   3x3 neighborhood; 7 loaded values serve all 4 positions per channel.
//   Bilinear evaluated as nested lerps so per-position state is just (wx, wy).
//   Cold exact-repair loop handles positions escaping the predicted window.

#define HW 16384

__device__ __forceinline__ unsigned long long pack2(float a, float b) {
    unsigned long long r;
    asm("mov.b64 %0, {%1, %2};" : "=l"(r) : "f"(a), "f"(b));
    return r;
}
__device__ __forceinline__ void ffma2(unsigned long long& d,
                                      unsigned long long a, unsigned long long b) {
    asm("fma.rn.f32x2 %0, %1, %2, %0;" : "+l"(d) : "l"(a), "l"(b));
}
__device__ __forceinline__ float2 unpack2(unsigned long long v) {
    float2 f;
    asm("mov.b64 {%0, %1}, %2;" : "=f"(f.x), "=f"(f.y) : "l"(v));
    return f;
}
__device__ __forceinline__ float clampf(float v, float lo, float hi) {
    return fminf(fmaxf(v, lo), hi);
}

__global__ __launch_bounds__(256, 5) void dysample_fused(
    const float* __restrict__ x,
    const float* __restrict__ w_off,
    const float* __restrict__ b_off,
    float* __restrict__ out)
{
    __shared__ __align__(16) float ws[64 * 32];     // [c][o]
    __shared__ __align__(16) float offs[32 * 128];  // [o][w]

    const int h   = blockIdx.x;
    const int b   = blockIdx.y;
    const int tid = threadIdx.x;

    // Stage weights transposed (8 KB, L2-hot after first wave).
    for (int i = tid; i < 2048; i += 256) {
        int c = i >> 5, o = i & 31;
        ws[i] = __ldg(&w_off[o * 64 + c]);
    }
    __syncthreads();

    // ---------------- Phase 1: 64->32 matvec for this row (packed f32x2) ----
    {
        const int p0 = (tid & 31) << 2;  // 4 consecutive pixels
        const int ob = (tid >> 5) << 2;  // 4 out-channels
        const float* xb = x + ((b * 64) << 14) + (h << 7) + p0;

        unsigned long long acc[4][2];    // [pixel][och-pair]
        #pragma unroll
        for (int p = 0; p < 4; p++) { acc[p][0] = 0ull; acc[p][1] = 0ull; }

        #pragma unroll 4
        for (int c = 0; c < 64; c++) {
            const float4 xv = __ldg(reinterpret_cast<const float4*>(xb + (c << 14)));
            const unsigned long long w01 =
                *reinterpret_cast<const unsigned long long*>(&ws[c * 32 + ob]);
            const unsigned long long w23 =
                *reinterpret_cast<const unsigned long long*>(&ws[c * 32 + ob + 2]);
            unsigned long long xp;
            xp = pack2(xv.x, xv.x); ffma2(acc[0][0], xp, w01); ffma2(acc[0][1], xp, w23);
            xp = pack2(xv.y, xv.y); ffma2(acc[1][0], xp, w01); ffma2(acc[1][1], xp, w23);
            xp = pack2(xv.z, xv.z); ffma2(acc[2][0], xp, w01); ffma2(acc[2][1], xp, w23);
            xp = pack2(xv.w, xv.w); ffma2(acc[3][0], xp, w01); ffma2(acc[3][1], xp, w23);
        }

        #pragma unroll
        for (int oo = 0; oo < 4; oo++) {
            const int o = ob + oo;
            const float bias = __ldg(&b_off[o]);
            const int dd = (o >> 2) & 1, ii = (o >> 1) & 1, jj = o & 1;
            const float initv = 0.25f * (float)((((dd ? ii : jj) << 1)) - 1);
            float* dst = &offs[(o << 7) + p0];
            #pragma unroll
            for (int p = 0; p < 4; p++) {
                float2 v = unpack2(acc[p][oo >> 1]);
                float a = (oo & 1) ? v.y : v.x;
                dst[p] = (a + bias) * 0.25f + initv;
            }
        }
    }
    __syncthreads();

    // ---------------- Phase 2: bilinear sampling --------------------------
    const int w = tid & 127;
    const int z = tid >> 7;
    const float fw = (float)w, fh = (float)h;
    const int wm = max(w - 1, 0), wp = min(w + 1, 127);
    const int hm = max(h - 1, 0), hp = min(h + 1, 127);
    const int rm = hm << 7, rc = h << 7, rp = hp << 7;

    for (int gpair = 0; gpair < 2; gpair++) {
        #pragma unroll
        for (int gg = 0; gg < 2; gg++) {        // compile-time parity
            const int g = gpair * 2 + gg;

            float WX[4], WY[4];
            int bad = 0;
            #pragma unroll
            for (int pos = 0; pos < 4; pos++) {  // pos = ri*2 + rj
                const int ri = pos >> 1, rj = pos & 1;
                const int s = gg ? ri : rj;      // compile-time
                const int o = (g << 2) + pos;
                const float offx = offs[(o << 7) + w];
                const float offy = offs[((o + 16) << 7) + w];
                const float ix = clampf(fw + offx, 0.0f, 127.0f);
                const float iy = clampf(fh + offy, 0.0f, 127.0f);
                const float x0f = floorf(ix), y0f = floorf(iy);
                const float wx = ix - x0f, wy = iy - y0f;
                const int x0 = (int)x0f, y0 = (int)y0f;
                const int x1 = min(x0 + 1, 127), y1 = min(y0 + 1, 127);
                const int cx0 = s ? w : wm,  cx1 = s ? wp : w;
                const int cy0 = s ? h : hm,  cy1 = s ? hp : h;
                // Exact iff column-0/row-0 taps match; mismatched col-1/row-1
                // taps carry zero weight when wx/wy == 0.
                const bool ok = (x0 == cx0) && (wx == 0.0f || x1 == cx1)
                             && (y0 == cy0) && (wy == 0.0f || y1 == cy1);
                if (!ok) bad |= (1 << pos);
                WX[pos] = wx;
                WY[pos] = wy;
            }

            const int cbase = b * 64 + (g << 4) + (z << 3);
            const float* pb = x + (cbase << 14);
            float* db = out + (cbase << 16) + (h << 9) + (w << 1);

            {   // fast path: 7 taps serve 4 outputs per channel (nested lerps)
                const float* p = pb;
                float* dst = db;
                #pragma unroll 2
                for (int cc = 0; cc < 8; cc++) {
                    const float r00 = __ldg(p + rm + wm), r01 = __ldg(p + rm + w);
                    const float r10 = __ldg(p + rc + wm), r11 = __ldg(p + rc + w);
                    const float r12 = __ldg(p + rc + wp);
                    const float r21 = __ldg(p + rp + w),  r22 = __ldg(p + rp + wp);
                    float v[4];
                    #pragma unroll
                    for (int pos = 0; pos < 4; pos++) {
                        const int s = gg ? (pos >> 1) : (pos & 1);  // compile-time
                        const float t00 = s ? r11 : r00, t01 = s ? r12 : r01;
                        const float t10 = s ? r21 : r10, t11 = s ? r22 : r11;
                        const float h0 = fmaf(WX[pos], t01 - t00, t00);
                        const float h1 = fmaf(WX[pos], t11 - t10, t10);
                        v[pos] = fmaf(WY[pos], h1 - h0, h0);
                    }
                    *reinterpret_cast<float2*>(dst)       = make_float2(v[0], v[1]);
                    *reinterpret_cast<float2*>(dst + 256) = make_float2(v[2], v[3]);
                    p += HW;
                    dst += 65536;
                }
            }

            if (bad) {  // cold exact repair (offset escaped predicted window)
                for (int pos = 0; pos < 4; pos++) {
                    if (!(bad & (1 << pos))) continue;
                    const int o = (g << 2) + pos;
                    const float offx = offs[(o << 7) + w];
                    const float offy = offs[((o + 16) << 7) + w];
                    const float ix = clampf(fw + offx, 0.0f, 127.0f);
                    const float iy = clampf(fh + offy, 0.0f, 127.0f);
                    const float x0f = floorf(ix), y0f = floorf(iy);
                    const float wx = ix - x0f, wy = iy - y0f;
                    const int x0 = (int)x0f, y0 = (int)y0f;
                    const int x1 = min(x0 + 1, 127), y1 = min(y0 + 1, 127);
                    const float* p = pb;
                    float* dst = db + (pos >> 1) * 256 + (pos & 1);
                    for (int cc = 0; cc < 8; cc++) {
                        const float u00 = __ldg(p + (y0 << 7) + x0);
                        const float u01 = __ldg(p + (y0 << 7) + x1);
                        const float u10 = __ldg(p + (y1 << 7) + x0);
                        const float u11 = __ldg(p + (y1 << 7) + x1);
                        *dst = (1.0f - wy) * ((1.0f - wx) * u00 + wx * u01)
                             + wy * ((1.0f - wx) * u10 + wx * u11);
                        p += HW;
                        dst += 65536;
                    }
                }
            }
        }
    }
}

extern "C" void kernel_launch(void* const* d_in, const int* in_sizes, int n_in,
                              void* d_out, int out_size)
{
    const float* x     = (const float*)d_in[0];  // [16,64,128,128]
    const float* w_off = (const float*)d_in[1];  // [32,64]
    const float* b_off = (const float*)d_in[2];  // [32]
    float* out = (float*)d_out;                  // [16,64,256,256]

    dysample_fused<<<dim3(128, 16), 256>>>(x, w_off, b_off, out);
    (void)in_sizes; (void)n_in; (void)out_size;
}